// round 1
// baseline (speedup 1.0000x reference)
#include <cuda_runtime.h>
#include <math.h>

#define NN   50000
#define EE   800000
#define PP   3
#define INF_ 128
#define HH   8
#define DD   32
#define HD   256   // H*D
#define KTOT 768   // P*H*D
#define EMB  128

// ---------------- scratch (static __device__; no allocations allowed) ---------
__device__ float g_feat[PP * NN * HD];   // per-metapath projected features
__device__ float g_out [PP * NN * HD];   // per-metapath weighted-sum accumulator, later elu'd
__device__ float g_el  [PP * NN * HH];
__device__ float g_er  [PP * NN * HH];
__device__ float g_m   [PP * NN * HH];
__device__ float g_den [PP * NN * HH];

// ---------------- helpers -----------------------------------------------------
__device__ __forceinline__ void atomicMaxF(float* addr, float v) {
    if (v >= 0.f) atomicMax((int*)addr, __float_as_int(v));
    else          atomicMin((unsigned int*)addr, __float_as_uint(v));
}

__device__ __forceinline__ void red_add_v4(float* addr, float4 v) {
    asm volatile("red.global.add.v4.f32 [%0], {%1,%2,%3,%4};"
                 :: "l"(addr), "f"(v.x), "f"(v.y), "f"(v.z), "f"(v.w) : "memory");
}

// ---------------- init: zero accumulators, m = -inf ---------------------------
__global__ void k_init() {
    int idx = blockIdx.x * 256 + threadIdx.x;
    if (idx < PP * NN * (HD / 4))
        ((float4*)g_out)[idx] = make_float4(0.f, 0.f, 0.f, 0.f);
    if (idx < PP * NN * HH) {
        g_m[idx]   = __int_as_float(0xff800000);  // -inf
        g_den[idx] = 0.f;
    }
}

// ---------------- feat = h @ W_p, fused el/er epilogue ------------------------
// grid (N/8, P), 256 threads. Thread t owns column t (= head t>>5, dim t&31)
// for 8 node rows. Warp w == head w -> shuffle-reduce gives el/er directly.
__global__ void k_feat(const float* __restrict__ hin, const float* __restrict__ fcw,
                       const float* __restrict__ al,  const float* __restrict__ ar)
{
    const int p  = blockIdx.y;
    const int nb = blockIdx.x * 8;
    const int t  = threadIdx.x;
    __shared__ float hs[8][INF_];
    {
        int r = t >> 5, c4 = t & 31;
        *(float4*)&hs[r][c4 * 4] = *(const float4*)(hin + (nb + r) * INF_ + c4 * 4);
    }
    __syncthreads();

    const float* W = fcw + p * INF_ * HD;
    float acc[8];
#pragma unroll
    for (int r = 0; r < 8; ++r) acc[r] = 0.f;
#pragma unroll 4
    for (int k = 0; k < INF_; ++k) {
        const float w = __ldg(W + k * HD + t);
#pragma unroll
        for (int r = 0; r < 8; ++r) acc[r] = fmaf(hs[r][k], w, acc[r]);
    }

    float* fp = g_feat + (p * NN + nb) * HD + t;
#pragma unroll
    for (int r = 0; r < 8; ++r) fp[r * HD] = acc[r];

    const int hg = t >> 5, lane = t & 31;
    const float alv = __ldg(al + p * HH * DD + hg * DD + lane);
    const float arv = __ldg(ar + p * HH * DD + hg * DD + lane);
#pragma unroll
    for (int r = 0; r < 8; ++r) {
        float sl = acc[r] * alv, sr = acc[r] * arv;
#pragma unroll
        for (int o = 16; o > 0; o >>= 1) {
            sl += __shfl_down_sync(0xffffffffu, sl, o);
            sr += __shfl_down_sync(0xffffffffu, sr, o);
        }
        if (lane == 0) {
            g_el[(p * NN + nb + r) * HH + hg] = sl;
            g_er[(p * NN + nb + r) * HH + hg] = sr;
        }
    }
}

// ---------------- edge pass 1: segment max of leaky_relu(el[src]+er[dst]) ----
__global__ void k_edge_max(const int* __restrict__ ei)
{
    const int p = blockIdx.y;
    const int e = blockIdx.x * 256 + threadIdx.x;
    const int src = ei[p * 2 * EE + e];
    const int dst = ei[p * 2 * EE + EE + e];
    const float4* elp = (const float4*)(g_el + (p * NN + src) * HH);
    const float4* erp = (const float4*)(g_er + (p * NN + dst) * HH);
    float4 a0 = elp[0], a1 = elp[1], b0 = erp[0], b1 = erp[1];
    float ev[8] = {a0.x + b0.x, a0.y + b0.y, a0.z + b0.z, a0.w + b0.w,
                   a1.x + b1.x, a1.y + b1.y, a1.z + b1.z, a1.w + b1.w};
    float* mp = g_m + (p * NN + dst) * HH;
#pragma unroll
    for (int h = 0; h < 8; ++h) {
        float x  = ev[h];
        float lr = fmaxf(x, 0.2f * x);
        atomicMaxF(mp + h, lr);
    }
}

// ---------------- edge pass 2: den += ex ; out[dst] += ex * feat[src] --------
// One warp per edge. Lanes 0..7 compute ex per head + den atomic; then all 32
// lanes stream the 256-float message as 64 float4 vector-reductions (2 iters).
__global__ void k_edge_agg(const int* __restrict__ ei)
{
    const int p    = blockIdx.y;
    const int wid  = threadIdx.x >> 5;
    const int lane = threadIdx.x & 31;
    const int e    = blockIdx.x * 8 + wid;
    const int src  = ei[p * 2 * EE + e];
    const int dst  = ei[p * 2 * EE + EE + e];
    const int bs   = (p * NN + src) * HH;
    const int bd   = (p * NN + dst) * HH;

    float ex = 0.f;
    if (lane < 8) {
        float x  = g_el[bs + lane] + g_er[bd + lane];
        float lr = fmaxf(x, 0.2f * x);
        ex = __expf(lr - g_m[bd + lane]);
        atomicAdd(&g_den[bd + lane], ex);
    }
    float exh[8];
#pragma unroll
    for (int j = 0; j < 8; ++j) exh[j] = __shfl_sync(0xffffffffu, ex, j);

    const float4* fsrc = (const float4*)g_feat + (p * NN + src) * (HD / 4);
    float4*       fdst = (float4*)      g_out  + (p * NN + dst) * (HD / 4);
#pragma unroll
    for (int it = 0; it < 2; ++it) {
        int   q = it * 32 + lane;
        float s = exh[q >> 3];
        float4 v = __ldg(&fsrc[q]);
        v.x *= s; v.y *= s; v.z *= s; v.w *= s;
        red_add_v4((float*)(fdst + q), v);
    }
}

// ---------------- per-node: out = elu(out / den) (den==0 -> 0) ---------------
__global__ void k_norm()
{
    int idx = blockIdx.x * 256 + threadIdx.x;
    if (idx >= PP * NN * (HD / 4)) return;
    int pn = idx >> 6;              // p*N + n
    int h  = (idx >> 3) & 7;
    float den = g_den[pn * HH + h];
    float inv = den > 0.f ? 1.f / den : 0.f;  // den==0 -> 0 -> elu(0)=0
    float4 v = ((float4*)g_out)[idx];
    v.x *= inv; v.y *= inv; v.z *= inv; v.w *= inv;
    v.x = v.x > 0.f ? v.x : expm1f(v.x);
    v.y = v.y > 0.f ? v.y : expm1f(v.y);
    v.z = v.z > 0.f ? v.z : expm1f(v.z);
    v.w = v.w > 0.f ? v.w : expm1f(v.w);
    ((float4*)g_out)[idx] = v;
}

// ---------------- final: out = z @ sem_w + sem_b ------------------------------
// z[n, p*256+c] lives at g_out[(p*N+n)*256 + c]. Block: 16 rows x 128 cols.
__global__ void k_sem(const float* __restrict__ sw, const float* __restrict__ sb,
                      float* __restrict__ out)
{
    const int nb   = blockIdx.x * 16;
    const int t    = threadIdx.x;
    const int col  = t & 127;
    const int half = t >> 7;           // 0/1 -> rows [0,8) / [8,16)
    __shared__ float zs[16][64];
    float acc[8];
#pragma unroll
    for (int r = 0; r < 8; ++r) acc[r] = 0.f;

    for (int k0 = 0; k0 < KTOT; k0 += 64) {
        const int p  = k0 >> 8;
        const int c0 = k0 & 255;
        {
            int r = t >> 4, q = t & 15;
            *(float4*)&zs[r][q * 4] =
                *(const float4*)(g_out + (p * NN + nb + r) * HD + c0 + q * 4);
        }
        __syncthreads();
#pragma unroll
        for (int kk = 0; kk < 64; ++kk) {
            const float w = __ldg(sw + (k0 + kk) * EMB + col);
#pragma unroll
            for (int r = 0; r < 8; ++r)
                acc[r] = fmaf(zs[half * 8 + r][kk], w, acc[r]);
        }
        __syncthreads();
    }
    const float b = __ldg(sb + col);
#pragma unroll
    for (int r = 0; r < 8; ++r)
        out[(nb + half * 8 + r) * EMB + col] = acc[r] + b;
}

// ---------------- launch ------------------------------------------------------
extern "C" void kernel_launch(void* const* d_in, const int* in_sizes, int n_in,
                              void* d_out, int out_size)
{
    const float* h   = (const float*)d_in[0];
    const int*   ei  = (const int*)  d_in[1];
    const float* fcw = (const float*)d_in[2];
    const float* al  = (const float*)d_in[3];
    const float* ar  = (const float*)d_in[4];
    const float* sw  = (const float*)d_in[5];
    const float* sb  = (const float*)d_in[6];
    float* out = (float*)d_out;

    k_init    <<<(PP * NN * (HD / 4) + 255) / 256, 256>>>();
    k_feat    <<<dim3(NN / 8, PP), 256>>>(h, fcw, al, ar);
    k_edge_max<<<dim3(EE / 256, PP), 256>>>(ei);
    k_edge_agg<<<dim3(EE / 8, PP), 256>>>(ei);
    k_norm    <<<(PP * NN * (HD / 4) + 255) / 256, 256>>>();
    k_sem     <<<NN / 16, 256>>>(sw, sb, out);
}

// round 2
// speedup vs baseline: 1.1030x; 1.1030x over previous
#include <cuda_runtime.h>
#include <math.h>

#define NN   50000
#define EE   800000
#define PP   3
#define INF_ 128
#define HH   8
#define DD   32
#define HD   256   // H*D
#define KTOT 768   // P*H*D
#define EMB  128
#define PN   (PP * NN)

// ---------------- scratch (static __device__; no allocations allowed) ---------
__device__ float g_feat[PP * NN * HD];   // projected features
__device__ float g_out [PP * NN * HD];   // per-metapath GAT output (post-ELU)
__device__ float g_el  [PP * NN * HH];
__device__ float g_er  [PP * NN * HH];
__device__ int   g_deg   [PN];
__device__ int   g_offs  [PN + 1];
__device__ int   g_cursor[PN];
__device__ int   g_srcl  [PP * EE];      // CSR-ordered src node ids

// ---------------- zero degree counters ----------------------------------------
__global__ void k_zero() {
    int idx = blockIdx.x * 256 + threadIdx.x;
    if (idx < PN) g_deg[idx] = 0;
}

// ---------------- feat = h @ W_p, fused el/er epilogue ------------------------
__global__ void k_feat(const float* __restrict__ hin, const float* __restrict__ fcw,
                       const float* __restrict__ al,  const float* __restrict__ ar)
{
    const int p  = blockIdx.y;
    const int nb = blockIdx.x * 8;
    const int t  = threadIdx.x;
    __shared__ float hs[8][INF_];
    {
        int r = t >> 5, c4 = t & 31;
        *(float4*)&hs[r][c4 * 4] = *(const float4*)(hin + (nb + r) * INF_ + c4 * 4);
    }
    __syncthreads();

    const float* W = fcw + p * INF_ * HD;
    float acc[8];
#pragma unroll
    for (int r = 0; r < 8; ++r) acc[r] = 0.f;
#pragma unroll 4
    for (int k = 0; k < INF_; ++k) {
        const float w = __ldg(W + k * HD + t);
#pragma unroll
        for (int r = 0; r < 8; ++r) acc[r] = fmaf(hs[r][k], w, acc[r]);
    }

    float* fp = g_feat + (p * NN + nb) * HD + t;
#pragma unroll
    for (int r = 0; r < 8; ++r) fp[r * HD] = acc[r];

    const int hg = t >> 5, lane = t & 31;
    const float alv = __ldg(al + p * HH * DD + hg * DD + lane);
    const float arv = __ldg(ar + p * HH * DD + hg * DD + lane);
#pragma unroll
    for (int r = 0; r < 8; ++r) {
        float sl = acc[r] * alv, sr = acc[r] * arv;
#pragma unroll
        for (int o = 16; o > 0; o >>= 1) {
            sl += __shfl_down_sync(0xffffffffu, sl, o);
            sr += __shfl_down_sync(0xffffffffu, sr, o);
        }
        if (lane == 0) {
            g_el[(p * NN + nb + r) * HH + hg] = sl;
            g_er[(p * NN + nb + r) * HH + hg] = sr;
        }
    }
}

// ---------------- CSR build: histogram ----------------------------------------
__global__ void k_hist(const int* __restrict__ ei) {
    const int p = blockIdx.y;
    const int e = blockIdx.x * 256 + threadIdx.x;
    const int dst = ei[p * 2 * EE + EE + e];
    atomicAdd(&g_deg[p * NN + dst], 1);
}

// ---------------- CSR build: exclusive scan (single block) --------------------
#define CHUNK 147   // ceil(150000 / 1024)
__global__ void k_scan() {
    __shared__ int s[1024];
    const int t = threadIdx.x;
    const int base = t * CHUNK;
    int sum = 0;
    for (int j = 0; j < CHUNK; ++j) {
        int idx = base + j;
        if (idx < PN) sum += g_deg[idx];
    }
    s[t] = sum;
    __syncthreads();
    for (int o = 1; o < 1024; o <<= 1) {
        int v = (t >= o) ? s[t - o] : 0;
        __syncthreads();
        s[t] += v;
        __syncthreads();
    }
    int run = (t > 0) ? s[t - 1] : 0;
    for (int j = 0; j < CHUNK; ++j) {
        int idx = base + j;
        if (idx < PN) {
            g_offs[idx]   = run;
            g_cursor[idx] = run;
            run += g_deg[idx];
        }
    }
    if (t == 1023) g_offs[PN] = s[1023];
}

// ---------------- CSR build: scatter src ids ----------------------------------
__global__ void k_scatter(const int* __restrict__ ei) {
    const int p = blockIdx.y;
    const int e = blockIdx.x * 256 + threadIdx.x;
    const int src = ei[p * 2 * EE + e];
    const int dst = ei[p * 2 * EE + EE + e];
    int pos = atomicAdd(&g_cursor[p * NN + dst], 1);
    g_srcl[pos] = src;
}

// ---------------- per-dst gather-aggregate + softmax + ELU (fused) ------------
// One warp per (p, dst). No max-shift: |e| <~ 3 so exp is safe; softmax ratio
// is shift-invariant. den accumulated redundantly per lane (no reduction).
__global__ void k_agg()
{
    const int p    = blockIdx.y;
    const int wid  = threadIdx.x >> 5;
    const int lane = threadIdx.x & 31;
    const int n    = blockIdx.x * 8 + wid;
    const int pn   = p * NN + n;
    const int h0   = lane >> 3;       // head for chunk q0 = lane
    const int h1   = h0 + 4;          // head for chunk q1 = 32 + lane
    const float er0 = g_er[pn * HH + h0];
    const float er1 = g_er[pn * HH + h1];

    const int beg = g_offs[pn];
    const int end = g_offs[pn + 1];

    float4 a0 = make_float4(0.f, 0.f, 0.f, 0.f), a1 = a0;
    float den0 = 0.f, den1 = 0.f;
    const float4* fb = (const float4*)g_feat;

    int i = beg;
    for (; i + 2 <= end; i += 2) {
        const int s0 = g_srcl[i];
        const int s1 = g_srcl[i + 1];
        const int b0 = p * NN + s0;
        const int b1 = p * NN + s1;
        float x00 = g_el[b0 * HH + h0] + er0;
        float x01 = g_el[b0 * HH + h1] + er1;
        float x10 = g_el[b1 * HH + h0] + er0;
        float x11 = g_el[b1 * HH + h1] + er1;
        float4 v00 = fb[b0 * 64 + lane];
        float4 v01 = fb[b0 * 64 + 32 + lane];
        float4 v10 = fb[b1 * 64 + lane];
        float4 v11 = fb[b1 * 64 + 32 + lane];
        float ex00 = __expf(fmaxf(x00, 0.2f * x00));
        float ex01 = __expf(fmaxf(x01, 0.2f * x01));
        float ex10 = __expf(fmaxf(x10, 0.2f * x10));
        float ex11 = __expf(fmaxf(x11, 0.2f * x11));
        den0 += ex00 + ex10;
        den1 += ex01 + ex11;
        a0.x = fmaf(ex00, v00.x, fmaf(ex10, v10.x, a0.x));
        a0.y = fmaf(ex00, v00.y, fmaf(ex10, v10.y, a0.y));
        a0.z = fmaf(ex00, v00.z, fmaf(ex10, v10.z, a0.z));
        a0.w = fmaf(ex00, v00.w, fmaf(ex10, v10.w, a0.w));
        a1.x = fmaf(ex01, v01.x, fmaf(ex11, v11.x, a1.x));
        a1.y = fmaf(ex01, v01.y, fmaf(ex11, v11.y, a1.y));
        a1.z = fmaf(ex01, v01.z, fmaf(ex11, v11.z, a1.z));
        a1.w = fmaf(ex01, v01.w, fmaf(ex11, v11.w, a1.w));
    }
    if (i < end) {
        const int s0 = g_srcl[i];
        const int b0 = p * NN + s0;
        float x00 = g_el[b0 * HH + h0] + er0;
        float x01 = g_el[b0 * HH + h1] + er1;
        float4 v00 = fb[b0 * 64 + lane];
        float4 v01 = fb[b0 * 64 + 32 + lane];
        float ex00 = __expf(fmaxf(x00, 0.2f * x00));
        float ex01 = __expf(fmaxf(x01, 0.2f * x01));
        den0 += ex00;
        den1 += ex01;
        a0.x = fmaf(ex00, v00.x, a0.x); a0.y = fmaf(ex00, v00.y, a0.y);
        a0.z = fmaf(ex00, v00.z, a0.z); a0.w = fmaf(ex00, v00.w, a0.w);
        a1.x = fmaf(ex01, v01.x, a1.x); a1.y = fmaf(ex01, v01.y, a1.y);
        a1.z = fmaf(ex01, v01.z, a1.z); a1.w = fmaf(ex01, v01.w, a1.w);
    }

    const float inv0 = den0 > 0.f ? 1.f / den0 : 0.f;
    const float inv1 = den1 > 0.f ? 1.f / den1 : 0.f;
    a0.x *= inv0; a0.y *= inv0; a0.z *= inv0; a0.w *= inv0;
    a1.x *= inv1; a1.y *= inv1; a1.z *= inv1; a1.w *= inv1;
    a0.x = a0.x > 0.f ? a0.x : expm1f(a0.x);
    a0.y = a0.y > 0.f ? a0.y : expm1f(a0.y);
    a0.z = a0.z > 0.f ? a0.z : expm1f(a0.z);
    a0.w = a0.w > 0.f ? a0.w : expm1f(a0.w);
    a1.x = a1.x > 0.f ? a1.x : expm1f(a1.x);
    a1.y = a1.y > 0.f ? a1.y : expm1f(a1.y);
    a1.z = a1.z > 0.f ? a1.z : expm1f(a1.z);
    a1.w = a1.w > 0.f ? a1.w : expm1f(a1.w);

    ((float4*)g_out)[pn * 64 + lane]      = a0;
    ((float4*)g_out)[pn * 64 + 32 + lane] = a1;
}

// ---------------- final: out = z @ sem_w + sem_b ------------------------------
__global__ void k_sem(const float* __restrict__ sw, const float* __restrict__ sb,
                      float* __restrict__ out)
{
    const int nb   = blockIdx.x * 16;
    const int t    = threadIdx.x;
    const int col  = t & 127;
    const int half = t >> 7;
    __shared__ float zs[16][64];
    float acc[8];
#pragma unroll
    for (int r = 0; r < 8; ++r) acc[r] = 0.f;

    for (int k0 = 0; k0 < KTOT; k0 += 64) {
        const int p  = k0 >> 8;
        const int c0 = k0 & 255;
        {
            int r = t >> 4, q = t & 15;
            *(float4*)&zs[r][q * 4] =
                *(const float4*)(g_out + (p * NN + nb + r) * HD + c0 + q * 4);
        }
        __syncthreads();
#pragma unroll
        for (int kk = 0; kk < 64; ++kk) {
            const float w = __ldg(sw + (k0 + kk) * EMB + col);
#pragma unroll
            for (int r = 0; r < 8; ++r)
                acc[r] = fmaf(zs[half * 8 + r][kk], w, acc[r]);
        }
        __syncthreads();
    }
    const float b = __ldg(sb + col);
#pragma unroll
    for (int r = 0; r < 8; ++r)
        out[(nb + half * 8 + r) * EMB + col] = acc[r] + b;
}

// ---------------- launch ------------------------------------------------------
extern "C" void kernel_launch(void* const* d_in, const int* in_sizes, int n_in,
                              void* d_out, int out_size)
{
    const float* h   = (const float*)d_in[0];
    const int*   ei  = (const int*)  d_in[1];
    const float* fcw = (const float*)d_in[2];
    const float* al  = (const float*)d_in[3];
    const float* ar  = (const float*)d_in[4];
    const float* sw  = (const float*)d_in[5];
    const float* sb  = (const float*)d_in[6];
    float* out = (float*)d_out;

    k_zero   <<<(PN + 255) / 256, 256>>>();
    k_hist   <<<dim3(EE / 256, PP), 256>>>(ei);
    k_scan   <<<1, 1024>>>();
    k_scatter<<<dim3(EE / 256, PP), 256>>>(ei);
    k_feat   <<<dim3(NN / 8, PP), 256>>>(h, fcw, al, ar);
    k_agg    <<<dim3(NN / 8, PP), 256>>>();
    k_sem    <<<NN / 16, 256>>>(sw, sb, out);
}

// round 4
// speedup vs baseline: 1.1833x; 1.0728x over previous
#include <cuda_runtime.h>
#include <cuda_fp16.h>
#include <math.h>

#define NN   50000
#define EE   800000
#define PP   3
#define INF_ 128
#define HH   8
#define DD   32
#define HD   256   // H*D
#define KTOT 768   // P*H*D
#define EMB  128
#define PN   (PP * NN)

// ---------------- scratch (static __device__; no allocations allowed) ---------
__device__ __half g_feat[PP * NN * HD];  // projected features (fp16, L2-resident)
__device__ float  g_out [PP * NN * HD];  // per-metapath GAT output (post-ELU)
__device__ float  g_el  [PP * NN * HH];
__device__ float  g_er  [PP * NN * HH];
__device__ int    g_deg   [PN];
__device__ int    g_offs  [PN + 1];
__device__ int    g_cursor[PN];
__device__ int    g_srcl  [PP * EE];     // CSR-ordered src node ids

// ---------------- zero degree counters ----------------------------------------
__global__ void k_zero() {
    int idx = blockIdx.x * 256 + threadIdx.x;
    if (idx < PN) g_deg[idx] = 0;
}

// ---------------- feat = h @ W_p (fp32 math, fp16 store), el/er epilogue ------
// 16 node rows per CTA, 256 threads; thread t owns column t.
__global__ void k_feat(const float* __restrict__ hin, const float* __restrict__ fcw,
                       const float* __restrict__ al,  const float* __restrict__ ar)
{
    const int p  = blockIdx.y;
    const int nb = blockIdx.x * 16;
    const int t  = threadIdx.x;
    __shared__ float hs[16][INF_];
#pragma unroll
    for (int j = 0; j < 2; ++j) {
        int idx = j * 256 + t;
        int r = idx >> 5, c4 = idx & 31;
        *(float4*)&hs[r][c4 * 4] = *(const float4*)(hin + (nb + r) * INF_ + c4 * 4);
    }
    __syncthreads();

    const float* W = fcw + p * INF_ * HD;
    float acc[16];
#pragma unroll
    for (int r = 0; r < 16; ++r) acc[r] = 0.f;
#pragma unroll 4
    for (int k = 0; k < INF_; ++k) {
        const float w = __ldg(W + k * HD + t);
#pragma unroll
        for (int r = 0; r < 16; ++r) acc[r] = fmaf(hs[r][k], w, acc[r]);
    }

    __half* fp = g_feat + (p * NN + nb) * HD + t;
#pragma unroll
    for (int r = 0; r < 16; ++r) fp[r * HD] = __float2half_rn(acc[r]);

    const int hg = t >> 5, lane = t & 31;
    const float alv = __ldg(al + p * HH * DD + hg * DD + lane);
    const float arv = __ldg(ar + p * HH * DD + hg * DD + lane);
#pragma unroll
    for (int r = 0; r < 16; ++r) {
        float sl = acc[r] * alv, sr = acc[r] * arv;
#pragma unroll
        for (int o = 16; o > 0; o >>= 1) {
            sl += __shfl_down_sync(0xffffffffu, sl, o);
            sr += __shfl_down_sync(0xffffffffu, sr, o);
        }
        if (lane == 0) {
            g_el[(p * NN + nb + r) * HH + hg] = sl;
            g_er[(p * NN + nb + r) * HH + hg] = sr;
        }
    }
}

// ---------------- CSR build: histogram ----------------------------------------
__global__ void k_hist(const int* __restrict__ ei) {
    const int p = blockIdx.y;
    const int e = blockIdx.x * 256 + threadIdx.x;
    const int dst = ei[p * 2 * EE + EE + e];
    atomicAdd(&g_deg[p * NN + dst], 1);
}

// ---------------- CSR build: exclusive scan (single block) --------------------
#define CHUNK 147   // ceil(150000 / 1024)
__global__ void k_scan() {
    __shared__ int s[1024];
    const int t = threadIdx.x;
    const int base = t * CHUNK;
    int sum = 0;
    for (int j = 0; j < CHUNK; ++j) {
        int idx = base + j;
        if (idx < PN) sum += g_deg[idx];
    }
    s[t] = sum;
    __syncthreads();
    for (int o = 1; o < 1024; o <<= 1) {
        int v = (t >= o) ? s[t - o] : 0;
        __syncthreads();
        s[t] += v;
        __syncthreads();
    }
    int run = (t > 0) ? s[t - 1] : 0;
    for (int j = 0; j < CHUNK; ++j) {
        int idx = base + j;
        if (idx < PN) {
            g_offs[idx]   = run;
            g_cursor[idx] = run;
            run += g_deg[idx];
        }
    }
    if (t == 1023) g_offs[PN] = s[1023];
}

// ---------------- CSR build: scatter src ids ----------------------------------
__global__ void k_scatter(const int* __restrict__ ei) {
    const int p = blockIdx.y;
    const int e = blockIdx.x * 256 + threadIdx.x;
    const int src = ei[p * 2 * EE + e];
    const int dst = ei[p * 2 * EE + EE + e];
    int pos = atomicAdd(&g_cursor[p * NN + dst], 1);
    g_srcl[pos] = src;
}

// ---------------- per-dst gather-aggregate + softmax + ELU (fused) ------------
// One warp per (p, dst). Lane q covers cols [8q, 8q+8) = head q>>2.
// Per edge: ONE uint4 load (8 halfs). No max-shift (|e| <~ 3, exp safe;
// softmax shift-invariant). den accumulated redundantly per lane.
__global__ void k_agg()
{
    const int p    = blockIdx.y;
    const int wid  = threadIdx.x >> 5;
    const int lane = threadIdx.x & 31;
    const int n    = blockIdx.x * 8 + wid;
    const int pn   = p * NN + n;
    const int hh   = lane >> 2;
    const float er_h = g_er[pn * HH + hh];

    const int beg = g_offs[pn];
    const int end = g_offs[pn + 1];

    float a[8];
#pragma unroll
    for (int j = 0; j < 8; ++j) a[j] = 0.f;
    float den = 0.f;
    const uint4* fb = (const uint4*)g_feat;   // 8 halfs per uint4; 32 per row

    int i = beg;
    for (; i + 2 <= end; i += 2) {
        const int b0 = p * NN + g_srcl[i];
        const int b1 = p * NN + g_srcl[i + 1];
        float x0 = g_el[b0 * HH + hh] + er_h;
        float x1 = g_el[b1 * HH + hh] + er_h;
        uint4 v0 = fb[b0 * 32 + lane];
        uint4 v1 = fb[b1 * 32 + lane];
        float ex0 = __expf(fmaxf(x0, 0.2f * x0));
        float ex1 = __expf(fmaxf(x1, 0.2f * x1));
        den += ex0 + ex1;
        const __half2* h0 = (const __half2*)&v0;
        const __half2* h1 = (const __half2*)&v1;
#pragma unroll
        for (int j = 0; j < 4; ++j) {
            float2 f0 = __half22float2(h0[j]);
            float2 f1 = __half22float2(h1[j]);
            a[2 * j]     = fmaf(ex0, f0.x, fmaf(ex1, f1.x, a[2 * j]));
            a[2 * j + 1] = fmaf(ex0, f0.y, fmaf(ex1, f1.y, a[2 * j + 1]));
        }
    }
    if (i < end) {
        const int b0 = p * NN + g_srcl[i];
        float x0 = g_el[b0 * HH + hh] + er_h;
        uint4 v0 = fb[b0 * 32 + lane];
        float ex0 = __expf(fmaxf(x0, 0.2f * x0));
        den += ex0;
        const __half2* h0 = (const __half2*)&v0;
#pragma unroll
        for (int j = 0; j < 4; ++j) {
            float2 f0 = __half22float2(h0[j]);
            a[2 * j]     = fmaf(ex0, f0.x, a[2 * j]);
            a[2 * j + 1] = fmaf(ex0, f0.y, a[2 * j + 1]);
        }
    }

    const float inv = den > 0.f ? 1.f / den : 0.f;
#pragma unroll
    for (int j = 0; j < 8; ++j) {
        float v = a[j] * inv;
        a[j] = v > 0.f ? v : expm1f(v);
    }
    float4* op = (float4*)(g_out + pn * HD + lane * 8);
    op[0] = make_float4(a[0], a[1], a[2], a[3]);
    op[1] = make_float4(a[4], a[5], a[6], a[7]);
}

// ---------------- final: out = z @ sem_w + sem_b ------------------------------
__global__ void k_sem(const float* __restrict__ sw, const float* __restrict__ sb,
                      float* __restrict__ out)
{
    const int nb   = blockIdx.x * 16;
    const int t    = threadIdx.x;
    const int col  = t & 127;
    const int half = t >> 7;
    __shared__ float zs[16][64];
    float acc[8];
#pragma unroll
    for (int r = 0; r < 8; ++r) acc[r] = 0.f;

    for (int k0 = 0; k0 < KTOT; k0 += 64) {
        const int p  = k0 >> 8;
        const int c0 = k0 & 255;
        {
            int r = t >> 4, q = t & 15;
            *(float4*)&zs[r][q * 4] =
                *(const float4*)(g_out + (p * NN + nb + r) * HD + c0 + q * 4);
        }
        __syncthreads();
#pragma unroll
        for (int kk = 0; kk < 64; ++kk) {
            const float w = __ldg(sw + (k0 + kk) * EMB + col);
#pragma unroll
            for (int r = 0; r < 8; ++r)
                acc[r] = fmaf(zs[half * 8 + r][kk], w, acc[r]);
        }
        __syncthreads();
    }
    const float b = __ldg(sb + col);
#pragma unroll
    for (int r = 0; r < 8; ++r)
        out[(nb + half * 8 + r) * EMB + col] = acc[r] + b;
}

// ---------------- launch ------------------------------------------------------
extern "C" void kernel_launch(void* const* d_in, const int* in_sizes, int n_in,
                              void* d_out, int out_size)
{
    const float* h   = (const float*)d_in[0];
    const int*   ei  = (const int*)  d_in[1];
    const float* fcw = (const float*)d_in[2];
    const float* al  = (const float*)d_in[3];
    const float* ar  = (const float*)d_in[4];
    const float* sw  = (const float*)d_in[5];
    const float* sb  = (const float*)d_in[6];
    float* out = (float*)d_out;

    k_zero   <<<(PN + 255) / 256, 256>>>();
    k_hist   <<<dim3(EE / 256, PP), 256>>>(ei);
    k_scan   <<<1, 1024>>>();
    k_scatter<<<dim3(EE / 256, PP), 256>>>(ei);
    k_feat   <<<dim3(NN / 16, PP), 256>>>(h, fcw, al, ar);
    k_agg    <<<dim3(NN / 8, PP), 256>>>();
    k_sem    <<<NN / 16, 256>>>(sw, sb, out);
}

// round 8
// speedup vs baseline: 1.7726x; 1.4980x over previous
#include <cuda_runtime.h>
#include <cuda_fp16.h>
#include <stdint.h>
#include <math.h>

#define NN   50000
#define EE   800000
#define PP   3
#define INF_ 128
#define HH   8
#define DD   32
#define HD   256   // H*D
#define KTOT 768   // P*H*D
#define EMB  128
#define PN   (PP * NN)

// ---------------- scratch (static __device__; no allocations allowed) ---------
__device__ __half g_feat[PP * NN * HD];  // projected features (fp16, L2-resident)
__device__ float  g_out [PP * NN * HD];  // per-metapath GAT output (post-ELU)
__device__ float  g_el  [PP * NN * HH];
__device__ float  g_er  [PP * NN * HH];
__device__ int    g_deg   [PN];
__device__ int    g_offs  [PN + 1];
__device__ int    g_cursor[PN];
__device__ int    g_srcl  [PP * EE];     // CSR-ordered src node ids

// ---------------- mma helpers --------------------------------------------------
__device__ __forceinline__ float tf32f(float x) {
    uint32_t u; asm("cvt.rna.tf32.f32 %0, %1;" : "=r"(u) : "f"(x));
    return __uint_as_float(u);
}
__device__ __forceinline__ void mma8(float* d, const uint32_t* a, const uint32_t* b) {
    asm volatile("mma.sync.aligned.m16n8k8.row.col.f32.tf32.tf32.f32 "
                 "{%0,%1,%2,%3},{%4,%5,%6,%7},{%8,%9},{%0,%1,%2,%3};"
                 : "+f"(d[0]), "+f"(d[1]), "+f"(d[2]), "+f"(d[3])
                 : "r"(a[0]), "r"(a[1]), "r"(a[2]), "r"(a[3]), "r"(b[0]), "r"(b[1]));
}

// ---------------- zero degree counters ----------------------------------------
__global__ void k_zero() {
    int idx = blockIdx.x * 256 + threadIdx.x;
    if (idx < PN) g_deg[idx] = 0;
}

// ---------------- feat = h @ W_p via tf32 MMA, fp16 store ---------------------
// CTA tile: 32 rows x 128 cols (blockIdx.z picks col half). 8 warps (2x4),
// warp tile 16x32 (1 mtile x 4 ntiles).
__global__ void k_feat(const float* __restrict__ hin, const float* __restrict__ fcw)
{
    __shared__ float Hs[32][132];
    __shared__ float Ws[32][136];
    const int p  = blockIdx.y, ch = blockIdx.z;
    const int nb = blockIdx.x * 32;
    const int t  = threadIdx.x, warp = t >> 5, lane = t & 31;
    const int g  = lane >> 2, tg = lane & 3;
    const int rw = warp >> 2, cw = warp & 3;

    // load Hs (32 x 128 fp32 -> tf32), row-guarded
    for (int i = t; i < 32 * 32; i += 256) {
        int r = i >> 5, q = i & 31;
        int row = nb + r;
        float4 v = make_float4(0.f, 0.f, 0.f, 0.f);
        if (row < NN) v = *(const float4*)(hin + row * INF_ + q * 4);
        v.x = tf32f(v.x); v.y = tf32f(v.y); v.z = tf32f(v.z); v.w = tf32f(v.w);
        *(float4*)&Hs[r][q * 4] = v;
    }

    float acc[4][4];
#pragma unroll
    for (int nt = 0; nt < 4; ++nt)
#pragma unroll
        for (int j = 0; j < 4; ++j) acc[nt][j] = 0.f;

    const float* Wbase = fcw + p * INF_ * HD + ch * 128;
    for (int kc = 0; kc < INF_; kc += 32) {
        __syncthreads();
        for (int i = t; i < 32 * 32; i += 256) {
            int kk = i >> 5, q = i & 31;
            float4 v = *(const float4*)(Wbase + (kc + kk) * HD + q * 4);
            v.x = tf32f(v.x); v.y = tf32f(v.y); v.z = tf32f(v.z); v.w = tf32f(v.w);
            *(float4*)&Ws[kk][q * 4] = v;
        }
        __syncthreads();
#pragma unroll
        for (int ks = 0; ks < 4; ++ks) {
            uint32_t a[4];
            const int arow = rw * 16 + g, acol = kc + ks * 8 + tg;
            a[0] = __float_as_uint(Hs[arow][acol]);
            a[1] = __float_as_uint(Hs[arow + 8][acol]);
            a[2] = __float_as_uint(Hs[arow][acol + 4]);
            a[3] = __float_as_uint(Hs[arow + 8][acol + 4]);
#pragma unroll
            for (int nt = 0; nt < 4; ++nt) {
                uint32_t b[2];
                const int bcol = cw * 32 + nt * 8 + g;
                b[0] = __float_as_uint(Ws[ks * 8 + tg][bcol]);
                b[1] = __float_as_uint(Ws[ks * 8 + tg + 4][bcol]);
                mma8(acc[nt], a, b);
            }
        }
    }

    const int row0 = nb + rw * 16 + g, row1 = row0 + 8;
    __half* fp = g_feat + (long)p * NN * HD + ch * 128;
#pragma unroll
    for (int nt = 0; nt < 4; ++nt) {
        const int col = cw * 32 + nt * 8 + 2 * tg;
        if (row0 < NN)
            *(__half2*)(fp + (long)row0 * HD + col) = __floats2half2_rn(acc[nt][0], acc[nt][1]);
        if (row1 < NN)
            *(__half2*)(fp + (long)row1 * HD + col) = __floats2half2_rn(acc[nt][2], acc[nt][3]);
    }
}

// ---------------- el/er from fp16 feat ----------------------------------------
// One warp per pn. Lane q covers cols [8q,8q+8) = head q>>2; quad-reduce.
__global__ void k_elr(const float* __restrict__ al, const float* __restrict__ ar)
{
    const int wid = threadIdx.x >> 5, lane = threadIdx.x & 31;
    const int pn = blockIdx.x * 8 + wid;
    const int p  = pn / NN;
    const uint4 v = *((const uint4*)(g_feat + (long)pn * HD) + lane);
    const __half2* hv = (const __half2*)&v;
    const int head = lane >> 2, dbase = (lane & 3) * 8;
    const float* alp = al + p * HH * DD + head * DD + dbase;
    const float* arp = ar + p * HH * DD + head * DD + dbase;
    float sl = 0.f, sr = 0.f;
#pragma unroll
    for (int j = 0; j < 4; ++j) {
        float2 f = __half22float2(hv[j]);
        sl += f.x * alp[2 * j] + f.y * alp[2 * j + 1];
        sr += f.x * arp[2 * j] + f.y * arp[2 * j + 1];
    }
    sl += __shfl_xor_sync(0xffffffffu, sl, 1);
    sl += __shfl_xor_sync(0xffffffffu, sl, 2);
    sr += __shfl_xor_sync(0xffffffffu, sr, 1);
    sr += __shfl_xor_sync(0xffffffffu, sr, 2);
    if ((lane & 3) == 0) {
        g_el[pn * HH + head] = sl;
        g_er[pn * HH + head] = sr;
    }
}

// ---------------- CSR build ----------------------------------------------------
__global__ void k_hist(const int* __restrict__ ei) {
    const int p = blockIdx.y;
    const int e = blockIdx.x * 256 + threadIdx.x;
    const int dst = ei[p * 2 * EE + EE + e];
    atomicAdd(&g_deg[p * NN + dst], 1);
}

#define CHUNK 147   // ceil(150000 / 1024)
__global__ void k_scan() {
    __shared__ int s[1024];
    const int t = threadIdx.x;
    const int base = t * CHUNK;
    int sum = 0;
    for (int j = 0; j < CHUNK; ++j) {
        int idx = base + j;
        if (idx < PN) sum += g_deg[idx];
    }
    s[t] = sum;
    __syncthreads();
    for (int o = 1; o < 1024; o <<= 1) {
        int v = (t >= o) ? s[t - o] : 0;
        __syncthreads();
        s[t] += v;
        __syncthreads();
    }
    int run = (t > 0) ? s[t - 1] : 0;
    for (int j = 0; j < CHUNK; ++j) {
        int idx = base + j;
        if (idx < PN) {
            g_offs[idx]   = run;
            g_cursor[idx] = run;
            run += g_deg[idx];
        }
    }
    if (t == 1023) g_offs[PN] = s[1023];
}

__global__ void k_scatter(const int* __restrict__ ei) {
    const int p = blockIdx.y;
    const int e = blockIdx.x * 256 + threadIdx.x;
    const int src = ei[p * 2 * EE + e];
    const int dst = ei[p * 2 * EE + EE + e];
    int pos = atomicAdd(&g_cursor[p * NN + dst], 1);
    g_srcl[pos] = src;
}

// ---------------- per-dst gather-aggregate + softmax + ELU (fused) ------------
__global__ void k_agg()
{
    const int p    = blockIdx.y;
    const int wid  = threadIdx.x >> 5;
    const int lane = threadIdx.x & 31;
    const int n    = blockIdx.x * 8 + wid;
    const int pn   = p * NN + n;
    const int hh   = lane >> 2;
    const float er_h = g_er[pn * HH + hh];

    const int beg = g_offs[pn];
    const int end = g_offs[pn + 1];

    float a[8];
#pragma unroll
    for (int j = 0; j < 8; ++j) a[j] = 0.f;
    float den = 0.f;
    const uint4* fb = (const uint4*)g_feat;

    int i = beg;
    for (; i + 2 <= end; i += 2) {
        const int b0 = p * NN + g_srcl[i];
        const int b1 = p * NN + g_srcl[i + 1];
        float x0 = g_el[b0 * HH + hh] + er_h;
        float x1 = g_el[b1 * HH + hh] + er_h;
        uint4 v0 = fb[b0 * 32 + lane];
        uint4 v1 = fb[b1 * 32 + lane];
        float ex0 = __expf(fmaxf(x0, 0.2f * x0));
        float ex1 = __expf(fmaxf(x1, 0.2f * x1));
        den += ex0 + ex1;
        const __half2* h0 = (const __half2*)&v0;
        const __half2* h1 = (const __half2*)&v1;
#pragma unroll
        for (int j = 0; j < 4; ++j) {
            float2 f0 = __half22float2(h0[j]);
            float2 f1 = __half22float2(h1[j]);
            a[2 * j]     = fmaf(ex0, f0.x, fmaf(ex1, f1.x, a[2 * j]));
            a[2 * j + 1] = fmaf(ex0, f0.y, fmaf(ex1, f1.y, a[2 * j + 1]));
        }
    }
    if (i < end) {
        const int b0 = p * NN + g_srcl[i];
        float x0 = g_el[b0 * HH + hh] + er_h;
        uint4 v0 = fb[b0 * 32 + lane];
        float ex0 = __expf(fmaxf(x0, 0.2f * x0));
        den += ex0;
        const __half2* h0 = (const __half2*)&v0;
#pragma unroll
        for (int j = 0; j < 4; ++j) {
            float2 f0 = __half22float2(h0[j]);
            a[2 * j]     = fmaf(ex0, f0.x, a[2 * j]);
            a[2 * j + 1] = fmaf(ex0, f0.y, a[2 * j + 1]);
        }
    }

    const float inv = den > 0.f ? 1.f / den : 0.f;
#pragma unroll
    for (int j = 0; j < 8; ++j) {
        float v = a[j] * inv;
        a[j] = v > 0.f ? v : expm1f(v);
    }
    float4* op = (float4*)(g_out + (long)pn * HD + lane * 8);
    op[0] = make_float4(a[0], a[1], a[2], a[3]);
    op[1] = make_float4(a[4], a[5], a[6], a[7]);
}

// ---------------- final: out = z @ sem_w + sem_b via tf32 MMA -----------------
// CTA tile 128x128, K=768 in chunks of 32. 8 warps (4x2), warp tile 32x64.
__global__ void k_sem(const float* __restrict__ sw, const float* __restrict__ sb,
                      float* __restrict__ out)
{
    __shared__ float Zs[128][36];
    __shared__ float Ws[32][136];
    const int nb = blockIdx.x * 128;
    const int t  = threadIdx.x, warp = t >> 5, lane = t & 31;
    const int g  = lane >> 2, tg = lane & 3;
    const int rw = warp >> 1, cw = warp & 1;

    float acc[2][8][4];
#pragma unroll
    for (int mt = 0; mt < 2; ++mt)
#pragma unroll
        for (int nt = 0; nt < 8; ++nt)
#pragma unroll
            for (int j = 0; j < 4; ++j) acc[mt][nt][j] = 0.f;

    for (int k0 = 0; k0 < KTOT; k0 += 32) {
        const int p  = k0 >> 8;
        const int c0 = k0 & 255;
        __syncthreads();
        // Zs: 128 rows x 32 k
        for (int i = t; i < 1024; i += 256) {
            int r = i >> 3, q = i & 7;
            int row = nb + r;
            float4 v = make_float4(0.f, 0.f, 0.f, 0.f);
            if (row < NN)
                v = *(const float4*)(g_out + ((long)p * NN + row) * HD + c0 + q * 4);
            v.x = tf32f(v.x); v.y = tf32f(v.y); v.z = tf32f(v.z); v.w = tf32f(v.w);
            *(float4*)&Zs[r][q * 4] = v;
        }
        // Ws: 32 k x 128 cols
        for (int i = t; i < 1024; i += 256) {
            int kk = i >> 5, q = i & 31;
            float4 v = *(const float4*)(sw + (long)(k0 + kk) * EMB + q * 4);
            v.x = tf32f(v.x); v.y = tf32f(v.y); v.z = tf32f(v.z); v.w = tf32f(v.w);
            *(float4*)&Ws[kk][q * 4] = v;
        }
        __syncthreads();
#pragma unroll
        for (int ks = 0; ks < 4; ++ks) {
            uint32_t a[2][4];
#pragma unroll
            for (int mt = 0; mt < 2; ++mt) {
                const int arow = rw * 32 + mt * 16 + g, acol = ks * 8 + tg;
                a[mt][0] = __float_as_uint(Zs[arow][acol]);
                a[mt][1] = __float_as_uint(Zs[arow + 8][acol]);
                a[mt][2] = __float_as_uint(Zs[arow][acol + 4]);
                a[mt][3] = __float_as_uint(Zs[arow + 8][acol + 4]);
            }
#pragma unroll
            for (int nt = 0; nt < 8; ++nt) {
                uint32_t b[2];
                const int bcol = cw * 64 + nt * 8 + g;
                b[0] = __float_as_uint(Ws[ks * 8 + tg][bcol]);
                b[1] = __float_as_uint(Ws[ks * 8 + tg + 4][bcol]);
                mma8(acc[0][nt], a[0], b);
                mma8(acc[1][nt], a[1], b);
            }
        }
    }

#pragma unroll
    for (int mt = 0; mt < 2; ++mt) {
        const int row0 = nb + rw * 32 + mt * 16 + g, row1 = row0 + 8;
#pragma unroll
        for (int nt = 0; nt < 8; ++nt) {
            const int col = cw * 64 + nt * 8 + 2 * tg;
            const float b0v = sb[col], b1v = sb[col + 1];
            if (row0 < NN) {
                out[(long)row0 * EMB + col]     = acc[mt][nt][0] + b0v;
                out[(long)row0 * EMB + col + 1] = acc[mt][nt][1] + b1v;
            }
            if (row1 < NN) {
                out[(long)row1 * EMB + col]     = acc[mt][nt][2] + b0v;
                out[(long)row1 * EMB + col + 1] = acc[mt][nt][3] + b1v;
            }
        }
    }
}

// ---------------- launch ------------------------------------------------------
extern "C" void kernel_launch(void* const* d_in, const int* in_sizes, int n_in,
                              void* d_out, int out_size)
{
    const float* h   = (const float*)d_in[0];
    const int*   ei  = (const int*)  d_in[1];
    const float* fcw = (const float*)d_in[2];
    const float* al  = (const float*)d_in[3];
    const float* ar  = (const float*)d_in[4];
    const float* sw  = (const float*)d_in[5];
    const float* sb  = (const float*)d_in[6];
    float* out = (float*)d_out;

    k_zero   <<<(PN + 255) / 256, 256>>>();
    k_hist   <<<dim3(EE / 256, PP), 256>>>(ei);
    k_scan   <<<1, 1024>>>();
    k_scatter<<<dim3(EE / 256, PP), 256>>>(ei);
    k_feat   <<<dim3((NN + 31) / 32, PP, 2), 256>>>(h, fcw);
    k_elr    <<<PN / 8, 256>>>(al, ar);
    k_agg    <<<dim3(NN / 8, PP), 256>>>();
    k_sem    <<<(NN + 127) / 128, 256>>>(sw, sb, out);
}

// round 9
// speedup vs baseline: 1.8144x; 1.0236x over previous
#include <cuda_runtime.h>
#include <cuda_fp16.h>
#include <stdint.h>
#include <math.h>

#define NN   50000
#define EE   800000
#define PP   3
#define INF_ 128
#define HH   8
#define DD   32
#define HD   256   // H*D
#define KTOT 768   // P*H*D
#define EMB  128
#define PN   (PP * NN)

// ---------------- scratch (static __device__; no allocations allowed) ---------
__device__ __half g_feat[PP * NN * HD];  // projected features (fp16, L2-resident)
__device__ float  g_out [PP * NN * HD];  // per-metapath GAT output (post-ELU)
__device__ float  g_el  [PP * NN * HH];
__device__ float  g_er  [PP * NN * HH];
__device__ int    g_deg   [PN];
__device__ int    g_offs  [PN + 1];
__device__ int    g_cursor[PN];
__device__ int    g_srcl  [PP * EE];     // CSR-ordered src node ids

// ---------------- mma helpers --------------------------------------------------
__device__ __forceinline__ float tf32f(float x) {
    uint32_t u; asm("cvt.rna.tf32.f32 %0, %1;" : "=r"(u) : "f"(x));
    return __uint_as_float(u);
}
__device__ __forceinline__ void mma8(float* d, const uint32_t* a, const uint32_t* b) {
    asm volatile("mma.sync.aligned.m16n8k8.row.col.f32.tf32.tf32.f32 "
                 "{%0,%1,%2,%3},{%4,%5,%6,%7},{%8,%9},{%0,%1,%2,%3};"
                 : "+f"(d[0]), "+f"(d[1]), "+f"(d[2]), "+f"(d[3])
                 : "r"(a[0]), "r"(a[1]), "r"(a[2]), "r"(a[3]), "r"(b[0]), "r"(b[1]));
}

// ---------------- zero degree counters ----------------------------------------
__global__ void k_zero() {
    int idx = blockIdx.x * 256 + threadIdx.x;
    if (idx < PN) g_deg[idx] = 0;
}

// ---------------- feat = h @ W_p via tf32 MMA, fp16 store ---------------------
__global__ void k_feat(const float* __restrict__ hin, const float* __restrict__ fcw)
{
    __shared__ float Hs[32][132];
    __shared__ float Ws[32][136];
    const int p  = blockIdx.y, ch = blockIdx.z;
    const int nb = blockIdx.x * 32;
    const int t  = threadIdx.x, warp = t >> 5, lane = t & 31;
    const int g  = lane >> 2, tg = lane & 3;
    const int rw = warp >> 2, cw = warp & 3;

    for (int i = t; i < 32 * 32; i += 256) {
        int r = i >> 5, q = i & 31;
        int row = nb + r;
        float4 v = make_float4(0.f, 0.f, 0.f, 0.f);
        if (row < NN) v = *(const float4*)(hin + row * INF_ + q * 4);
        v.x = tf32f(v.x); v.y = tf32f(v.y); v.z = tf32f(v.z); v.w = tf32f(v.w);
        *(float4*)&Hs[r][q * 4] = v;
    }

    float acc[4][4];
#pragma unroll
    for (int nt = 0; nt < 4; ++nt)
#pragma unroll
        for (int j = 0; j < 4; ++j) acc[nt][j] = 0.f;

    const float* Wbase = fcw + p * INF_ * HD + ch * 128;
    for (int kc = 0; kc < INF_; kc += 32) {
        __syncthreads();
        for (int i = t; i < 32 * 32; i += 256) {
            int kk = i >> 5, q = i & 31;
            float4 v = *(const float4*)(Wbase + (kc + kk) * HD + q * 4);
            v.x = tf32f(v.x); v.y = tf32f(v.y); v.z = tf32f(v.z); v.w = tf32f(v.w);
            *(float4*)&Ws[kk][q * 4] = v;
        }
        __syncthreads();
#pragma unroll
        for (int ks = 0; ks < 4; ++ks) {
            uint32_t a[4];
            const int arow = rw * 16 + g, acol = kc + ks * 8 + tg;
            a[0] = __float_as_uint(Hs[arow][acol]);
            a[1] = __float_as_uint(Hs[arow + 8][acol]);
            a[2] = __float_as_uint(Hs[arow][acol + 4]);
            a[3] = __float_as_uint(Hs[arow + 8][acol + 4]);
#pragma unroll
            for (int nt = 0; nt < 4; ++nt) {
                uint32_t b[2];
                const int bcol = cw * 32 + nt * 8 + g;
                b[0] = __float_as_uint(Ws[ks * 8 + tg][bcol]);
                b[1] = __float_as_uint(Ws[ks * 8 + tg + 4][bcol]);
                mma8(acc[nt], a, b);
            }
        }
    }

    const int row0 = nb + rw * 16 + g, row1 = row0 + 8;
    __half* fp = g_feat + (long)p * NN * HD + ch * 128;
#pragma unroll
    for (int nt = 0; nt < 4; ++nt) {
        const int col = cw * 32 + nt * 8 + 2 * tg;
        if (row0 < NN)
            *(__half2*)(fp + (long)row0 * HD + col) = __floats2half2_rn(acc[nt][0], acc[nt][1]);
        if (row1 < NN)
            *(__half2*)(fp + (long)row1 * HD + col) = __floats2half2_rn(acc[nt][2], acc[nt][3]);
    }
}

// ---------------- el/er from fp16 feat ----------------------------------------
__global__ void k_elr(const float* __restrict__ al, const float* __restrict__ ar)
{
    const int wid = threadIdx.x >> 5, lane = threadIdx.x & 31;
    const int pn = blockIdx.x * 8 + wid;
    const int p  = pn / NN;
    const uint4 v = *((const uint4*)(g_feat + (long)pn * HD) + lane);
    const __half2* hv = (const __half2*)&v;
    const int head = lane >> 2, dbase = (lane & 3) * 8;
    const float* alp = al + p * HH * DD + head * DD + dbase;
    const float* arp = ar + p * HH * DD + head * DD + dbase;
    float sl = 0.f, sr = 0.f;
#pragma unroll
    for (int j = 0; j < 4; ++j) {
        float2 f = __half22float2(hv[j]);
        sl += f.x * alp[2 * j] + f.y * alp[2 * j + 1];
        sr += f.x * arp[2 * j] + f.y * arp[2 * j + 1];
    }
    sl += __shfl_xor_sync(0xffffffffu, sl, 1);
    sl += __shfl_xor_sync(0xffffffffu, sl, 2);
    sr += __shfl_xor_sync(0xffffffffu, sr, 1);
    sr += __shfl_xor_sync(0xffffffffu, sr, 2);
    if ((lane & 3) == 0) {
        g_el[pn * HH + head] = sl;
        g_er[pn * HH + head] = sr;
    }
}

// ---------------- CSR build ----------------------------------------------------
__global__ void k_hist(const int* __restrict__ ei) {
    const int p = blockIdx.y;
    const int e = blockIdx.x * 256 + threadIdx.x;
    const int dst = ei[p * 2 * EE + EE + e];
    atomicAdd(&g_deg[p * NN + dst], 1);
}

#define CHUNK 147   // ceil(150000 / 1024)
__global__ void k_scan() {
    __shared__ int s[1024];
    const int t = threadIdx.x;
    const int base = t * CHUNK;
    int sum = 0;
    for (int j = 0; j < CHUNK; ++j) {
        int idx = base + j;
        if (idx < PN) sum += g_deg[idx];
    }
    s[t] = sum;
    __syncthreads();
    for (int o = 1; o < 1024; o <<= 1) {
        int v = (t >= o) ? s[t - o] : 0;
        __syncthreads();
        s[t] += v;
        __syncthreads();
    }
    int run = (t > 0) ? s[t - 1] : 0;
    for (int j = 0; j < CHUNK; ++j) {
        int idx = base + j;
        if (idx < PN) {
            g_offs[idx]   = run;
            g_cursor[idx] = run;
            run += g_deg[idx];
        }
    }
    if (t == 1023) g_offs[PN] = s[1023];
}

__global__ void k_scatter(const int* __restrict__ ei) {
    const int p = blockIdx.y;
    const int e = blockIdx.x * 256 + threadIdx.x;
    const int src = ei[p * 2 * EE + e];
    const int dst = ei[p * 2 * EE + EE + e];
    int pos = atomicAdd(&g_cursor[p * NN + dst], 1);
    g_srcl[pos] = src;
}

// ---------------- per-dst gather-aggregate + softmax + ELU (fused) ------------
// One warp per (p, dst). 4-edge blocked mainloop: all 4 srcl indices loaded
// first, then 4 el loads + 4 uint4 feat loads issued back-to-back -> MLP ~4-8
// to cover L2 latency (kernel was latency-bound at unroll 2).
__global__ void k_agg()
{
    const int p    = blockIdx.y;
    const int wid  = threadIdx.x >> 5;
    const int lane = threadIdx.x & 31;
    const int n    = blockIdx.x * 8 + wid;
    const int pn   = p * NN + n;
    const int hh   = lane >> 2;
    const float er_h = g_er[pn * HH + hh];

    const int beg = g_offs[pn];
    const int end = g_offs[pn + 1];

    float a[8];
#pragma unroll
    for (int j = 0; j < 8; ++j) a[j] = 0.f;
    float den = 0.f;
    const uint4* fb = (const uint4*)g_feat;

    int i = beg;
    for (; i + 4 <= end; i += 4) {
        // phase 1: independent index loads
        const int b0 = p * NN + __ldg(&g_srcl[i]);
        const int b1 = p * NN + __ldg(&g_srcl[i + 1]);
        const int b2 = p * NN + __ldg(&g_srcl[i + 2]);
        const int b3 = p * NN + __ldg(&g_srcl[i + 3]);
        // phase 2: issue all 8 loads before consuming any
        const float x0 = __ldg(&g_el[b0 * HH + hh]);
        const float x1 = __ldg(&g_el[b1 * HH + hh]);
        const float x2 = __ldg(&g_el[b2 * HH + hh]);
        const float x3 = __ldg(&g_el[b3 * HH + hh]);
        const uint4 v0 = __ldg(&fb[b0 * 32 + lane]);
        const uint4 v1 = __ldg(&fb[b1 * 32 + lane]);
        const uint4 v2 = __ldg(&fb[b2 * 32 + lane]);
        const uint4 v3 = __ldg(&fb[b3 * 32 + lane]);
        // phase 3: compute
        float y0 = x0 + er_h, y1 = x1 + er_h, y2 = x2 + er_h, y3 = x3 + er_h;
        const float ex0 = __expf(fmaxf(y0, 0.2f * y0));
        const float ex1 = __expf(fmaxf(y1, 0.2f * y1));
        const float ex2 = __expf(fmaxf(y2, 0.2f * y2));
        const float ex3 = __expf(fmaxf(y3, 0.2f * y3));
        den += (ex0 + ex1) + (ex2 + ex3);
        const __half2* h0 = (const __half2*)&v0;
        const __half2* h1 = (const __half2*)&v1;
        const __half2* h2 = (const __half2*)&v2;
        const __half2* h3 = (const __half2*)&v3;
#pragma unroll
        for (int j = 0; j < 4; ++j) {
            float2 f0 = __half22float2(h0[j]);
            float2 f1 = __half22float2(h1[j]);
            float2 f2 = __half22float2(h2[j]);
            float2 f3 = __half22float2(h3[j]);
            a[2 * j]     = fmaf(ex0, f0.x, fmaf(ex1, f1.x, fmaf(ex2, f2.x, fmaf(ex3, f3.x, a[2 * j]))));
            a[2 * j + 1] = fmaf(ex0, f0.y, fmaf(ex1, f1.y, fmaf(ex2, f2.y, fmaf(ex3, f3.y, a[2 * j + 1]))));
        }
    }
    for (; i < end; ++i) {
        const int b0 = p * NN + __ldg(&g_srcl[i]);
        const float x0 = __ldg(&g_el[b0 * HH + hh]) + er_h;
        const uint4 v0 = __ldg(&fb[b0 * 32 + lane]);
        const float ex0 = __expf(fmaxf(x0, 0.2f * x0));
        den += ex0;
        const __half2* h0 = (const __half2*)&v0;
#pragma unroll
        for (int j = 0; j < 4; ++j) {
            float2 f0 = __half22float2(h0[j]);
            a[2 * j]     = fmaf(ex0, f0.x, a[2 * j]);
            a[2 * j + 1] = fmaf(ex0, f0.y, a[2 * j + 1]);
        }
    }

    const float inv = den > 0.f ? 1.f / den : 0.f;
#pragma unroll
    for (int j = 0; j < 8; ++j) {
        float v = a[j] * inv;
        a[j] = v > 0.f ? v : expm1f(v);
    }
    float4* op = (float4*)(g_out + (long)pn * HD + lane * 8);
    op[0] = make_float4(a[0], a[1], a[2], a[3]);
    op[1] = make_float4(a[4], a[5], a[6], a[7]);
}

// ---------------- final: out = z @ sem_w + sem_b via tf32 MMA -----------------
__global__ void k_sem(const float* __restrict__ sw, const float* __restrict__ sb,
                      float* __restrict__ out)
{
    __shared__ float Zs[128][36];
    __shared__ float Ws[32][136];
    const int nb = blockIdx.x * 128;
    const int t  = threadIdx.x, warp = t >> 5, lane = t & 31;
    const int g  = lane >> 2, tg = lane & 3;
    const int rw = warp >> 1, cw = warp & 1;

    float acc[2][8][4];
#pragma unroll
    for (int mt = 0; mt < 2; ++mt)
#pragma unroll
        for (int nt = 0; nt < 8; ++nt)
#pragma unroll
            for (int j = 0; j < 4; ++j) acc[mt][nt][j] = 0.f;

    for (int k0 = 0; k0 < KTOT; k0 += 32) {
        const int p  = k0 >> 8;
        const int c0 = k0 & 255;
        __syncthreads();
        for (int i = t; i < 1024; i += 256) {
            int r = i >> 3, q = i & 7;
            int row = nb + r;
            float4 v = make_float4(0.f, 0.f, 0.f, 0.f);
            if (row < NN)
                v = *(const float4*)(g_out + ((long)p * NN + row) * HD + c0 + q * 4);
            v.x = tf32f(v.x); v.y = tf32f(v.y); v.z = tf32f(v.z); v.w = tf32f(v.w);
            *(float4*)&Zs[r][q * 4] = v;
        }
        for (int i = t; i < 1024; i += 256) {
            int kk = i >> 5, q = i & 31;
            float4 v = *(const float4*)(sw + (long)(k0 + kk) * EMB + q * 4);
            v.x = tf32f(v.x); v.y = tf32f(v.y); v.z = tf32f(v.z); v.w = tf32f(v.w);
            *(float4*)&Ws[kk][q * 4] = v;
        }
        __syncthreads();
#pragma unroll
        for (int ks = 0; ks < 4; ++ks) {
            uint32_t a[2][4];
#pragma unroll
            for (int mt = 0; mt < 2; ++mt) {
                const int arow = rw * 32 + mt * 16 + g, acol = ks * 8 + tg;
                a[mt][0] = __float_as_uint(Zs[arow][acol]);
                a[mt][1] = __float_as_uint(Zs[arow + 8][acol]);
                a[mt][2] = __float_as_uint(Zs[arow][acol + 4]);
                a[mt][3] = __float_as_uint(Zs[arow + 8][acol + 4]);
            }
#pragma unroll
            for (int nt = 0; nt < 8; ++nt) {
                uint32_t b[2];
                const int bcol = cw * 64 + nt * 8 + g;
                b[0] = __float_as_uint(Ws[ks * 8 + tg][bcol]);
                b[1] = __float_as_uint(Ws[ks * 8 + tg + 4][bcol]);
                mma8(acc[0][nt], a[0], b);
                mma8(acc[1][nt], a[1], b);
            }
        }
    }

#pragma unroll
    for (int mt = 0; mt < 2; ++mt) {
        const int row0 = nb + rw * 32 + mt * 16 + g, row1 = row0 + 8;
#pragma unroll
        for (int nt = 0; nt < 8; ++nt) {
            const int col = cw * 64 + nt * 8 + 2 * tg;
            const float b0v = sb[col], b1v = sb[col + 1];
            if (row0 < NN) {
                out[(long)row0 * EMB + col]     = acc[mt][nt][0] + b0v;
                out[(long)row0 * EMB + col + 1] = acc[mt][nt][1] + b1v;
            }
            if (row1 < NN) {
                out[(long)row1 * EMB + col]     = acc[mt][nt][2] + b0v;
                out[(long)row1 * EMB + col + 1] = acc[mt][nt][3] + b1v;
            }
        }
    }
}

// ---------------- launch ------------------------------------------------------
extern "C" void kernel_launch(void* const* d_in, const int* in_sizes, int n_in,
                              void* d_out, int out_size)
{
    const float* h   = (const float*)d_in[0];
    const int*   ei  = (const int*)  d_in[1];
    const float* fcw = (const float*)d_in[2];
    const float* al  = (const float*)d_in[3];
    const float* ar  = (const float*)d_in[4];
    const float* sw  = (const float*)d_in[5];
    const float* sb  = (const float*)d_in[6];
    float* out = (float*)d_out;

    k_zero   <<<(PN + 255) / 256, 256>>>();
    k_hist   <<<dim3(EE / 256, PP), 256>>>(ei);
    k_scan   <<<1, 1024>>>();
    k_scatter<<<dim3(EE / 256, PP), 256>>>(ei);
    k_feat   <<<dim3((NN + 31) / 32, PP, 2), 256>>>(h, fcw);
    k_elr    <<<PN / 8, 256>>>(al, ar);
    k_agg    <<<dim3(NN / 8, PP), 256>>>();
    k_sem    <<<(NN + 127) / 128, 256>>>(sw, sb, out);
}